// round 16
// baseline (speedup 1.0000x reference)
#include <cuda_runtime.h>

// Problem constants
#define NP    64     // B*NUM_PARTS = 16*4
#define PC    32     // channels per part
#define HH    64
#define WW    512
#define HB    8      // h rows per K4 CTA
#define WQ    128    // w quarter width per K4 CTA

typedef unsigned long long u64;

__device__ __forceinline__ u64 pk2(float a, float b) {
    u64 r; asm("mov.b64 %0, {%1,%2};" : "=l"(r) : "f"(a), "f"(b)); return r;
}
__device__ __forceinline__ void upk2(u64 v, float& a, float& b) {
    asm("mov.b64 {%0,%1}, %2;" : "=f"(a), "=f"(b) : "l"(v));
}
__device__ __forceinline__ void ffma2(u64& d, u64 a, u64 b) {
    asm("fma.rn.f32x2 %0, %1, %2, %0;" : "+l"(d) : "l"(a), "l"(b));
}

// lean branchless sigmoid: FMUL+EX2 (expf) + FADD + MUFU.RCP.
// t<<0: exp(-t)=inf -> rcp=0 (correct); t>>0: exp(-t)=0 -> rcp(1)=1 (correct).
__device__ __forceinline__ float sigf(float t) {
    float e = __expf(-t);
    float d = 1.0f + e;
    float r; asm("rcp.approx.f32 %0, %1;" : "=f"(r) : "f"(d));
    return r;
}

// Scratch (device globals, allocation-free)
__device__ float g_havg[NP * PC * HH];
__device__ float g_hmax[NP * PC * HH];
__device__ float g_wavg[NP * PC * WW];
__device__ float g_wmax[NP * PC * WW];
__device__ float g_ph[NP * PC * HH];
__device__ float g_pw[NP * PC * WW];
__device__ int   g_sink;

// dummy launch to keep the ncu -s 5 -c 1 capture window on k4_apply
__global__ void k_dummy(int* sink) { if (threadIdx.x == 1024) *sink = 0; }

// ---------------------------------------------------------------------------
// K1: per-(n,c) slice stats. Quad-level shfl reduce + smem partials.
// grid 2048, 256 threads
// ---------------------------------------------------------------------------
__global__ __launch_bounds__(256) void k1_stats(const float* __restrict__ x) {
    const int nc  = blockIdx.x;
    const int tid = threadIdx.x;
    const int r2  = tid >> 7;        // 0/1: which row of a 2-row stripe
    const int c4  = tid & 127;       // float4 column 0..127

    const float4* xs = reinterpret_cast<const float4*>(x + (size_t)nc * HH * WW);

    __shared__ float rs[HH][33], rm[HH][33];   // 33: kill final-reduce bank conflict
    __shared__ float csh[WW], cmh[WW];

    float cs0 = 0.f, cs1 = 0.f, cs2 = 0.f, cs3 = 0.f;
    float cm0 = -3.4e38f, cm1 = -3.4e38f, cm2 = -3.4e38f, cm3 = -3.4e38f;
    const int q = c4 >> 2;

    for (int h0 = 0; h0 < HH; h0 += 2) {
        const int h = h0 + r2;
        float4 v = xs[h * 128 + c4];
        cs0 += v.x; cs1 += v.y; cs2 += v.z; cs3 += v.w;
        cm0 = fmaxf(cm0, v.x); cm1 = fmaxf(cm1, v.y);
        cm2 = fmaxf(cm2, v.z); cm3 = fmaxf(cm3, v.w);
        float s = (v.x + v.y) + (v.z + v.w);
        float m = fmaxf(fmaxf(v.x, v.y), fmaxf(v.z, v.w));
        s += __shfl_xor_sync(0xffffffffu, s, 1);
        m  = fmaxf(m, __shfl_xor_sync(0xffffffffu, m, 1));
        s += __shfl_xor_sync(0xffffffffu, s, 2);
        m  = fmaxf(m, __shfl_xor_sync(0xffffffffu, m, 2));
        if ((tid & 3) == 0) { rs[h][q] = s; rm[h][q] = m; }
    }
    __syncthreads();

    if (tid < HH) {
        float s = 0.f, m = -3.4e38f;
        #pragma unroll
        for (int k = 0; k < 32; k++) { s += rs[tid][k]; m = fmaxf(m, rm[tid][k]); }
        g_havg[nc * HH + tid] = s * (1.0f / (float)WW);
        g_hmax[nc * HH + tid] = m;
    }

    if (r2 == 0) {
        csh[c4 * 4 + 0] = cs0; csh[c4 * 4 + 1] = cs1; csh[c4 * 4 + 2] = cs2; csh[c4 * 4 + 3] = cs3;
        cmh[c4 * 4 + 0] = cm0; cmh[c4 * 4 + 1] = cm1; cmh[c4 * 4 + 2] = cm2; cmh[c4 * 4 + 3] = cm3;
    }
    __syncthreads();
    if (r2 == 1) {
        const int w = c4 * 4;
        g_wavg[nc * WW + w + 0] = (cs0 + csh[w + 0]) * (1.0f / (float)HH);
        g_wavg[nc * WW + w + 1] = (cs1 + csh[w + 1]) * (1.0f / (float)HH);
        g_wavg[nc * WW + w + 2] = (cs2 + csh[w + 2]) * (1.0f / (float)HH);
        g_wavg[nc * WW + w + 3] = (cs3 + csh[w + 3]) * (1.0f / (float)HH);
        g_wmax[nc * WW + w + 0] = fmaxf(cm0, cmh[w + 0]);
        g_wmax[nc * WW + w + 1] = fmaxf(cm1, cmh[w + 1]);
        g_wmax[nc * WW + w + 2] = fmaxf(cm2, cmh[w + 2]);
        g_wmax[nc * WW + w + 3] = fmaxf(cm3, cmh[w + 3]);
    }
}

// ---------------------------------------------------------------------------
// K23: merged ph conv (blocks [0,64)) + pw conv (blocks [64,320), o split 4-way)
// 256 threads. pw part now reads g_wavg/g_wmax directly from L2 (no 128KB smem
// staging -> ~6 CTAs/SM instead of 1). dyn smem = ph need = 40960 B.
// ---------------------------------------------------------------------------
__global__ __launch_bounds__(256) void k23(const float* __restrict__ w_h,
                                           const float* __restrict__ b_h,
                                           const float* __restrict__ w_w,
                                           const float* __restrict__ b_w) {
    extern __shared__ float sm[];
    const int bid = blockIdx.x;
    const int tid = threadIdx.x;

    if (bid < 64) {
        // ---------------- ph: conv 3x2 pad(h)=1 + relu + softmax over h ----
        const int n = bid;
        float* ha = sm;                 // [32][64]
        float* hm = sm + PC * HH;       // [32][64]
        float* wh = sm + 2 * PC * HH;   // 6144

        for (int idx = tid; idx < PC * HH; idx += 256) {
            ha[idx] = g_havg[n * PC * HH + idx];
            hm[idx] = g_hmax[n * PC * HH + idx];
        }
        for (int idx = tid; idx < PC * PC * 6; idx += 256) wh[idx] = w_h[idx];
        __syncthreads();

        const int o  = tid >> 3;     // 0..31
        const int j  = tid & 7;      // 8 threads per o, 8 h each
        const int hb = j * 8;

        float acc[8];
        const float bo = b_h[o];
        #pragma unroll
        for (int t = 0; t < 8; t++) acc[t] = bo;

        for (int i = 0; i < PC; i++) {
            const float* wp = &wh[(o * PC + i) * 6];
            const float w00 = wp[0], w01 = wp[1], w10 = wp[2], w11 = wp[3], w20 = wp[4], w21 = wp[5];
            const float* A = ha + i * HH;
            const float* M = hm + i * HH;
            float wA[10], wM[10];
            wA[0] = (hb > 0) ? A[hb - 1] : 0.f;
            wM[0] = (hb > 0) ? M[hb - 1] : 0.f;
            #pragma unroll
            for (int t = 0; t < 8; t++) { wA[t + 1] = A[hb + t]; wM[t + 1] = M[hb + t]; }
            wA[9] = (hb + 8 < HH) ? A[hb + 8] : 0.f;
            wM[9] = (hb + 8 < HH) ? M[hb + 8] : 0.f;
            #pragma unroll
            for (int t = 0; t < 8; t++) {
                acc[t] += wA[t] * w00 + wM[t] * w01
                        + wA[t + 1] * w10 + wM[t + 1] * w11
                        + wA[t + 2] * w20 + wM[t + 2] * w21;
            }
        }

        float lm = -3.4e38f;
        #pragma unroll
        for (int t = 0; t < 8; t++) { acc[t] = fmaxf(acc[t], 0.f); lm = fmaxf(lm, acc[t]); }
        #pragma unroll
        for (int off = 1; off <= 4; off <<= 1) lm = fmaxf(lm, __shfl_xor_sync(0xffffffffu, lm, off));
        float ls = 0.f;
        #pragma unroll
        for (int t = 0; t < 8; t++) { acc[t] = __expf(acc[t] - lm); ls += acc[t]; }
        #pragma unroll
        for (int off = 1; off <= 4; off <<= 1) ls += __shfl_xor_sync(0xffffffffu, ls, off);
        const float inv = 1.0f / ls;
        #pragma unroll
        for (int t = 0; t < 8; t++) g_ph[(n * PC + o) * HH + hb + t] = acc[t] * inv;
    } else {
        // ---------------- pw: conv 2x3 pad(w)=1 + relu + softmax over w ----
        const int b2 = bid - 64;
        const int n  = b2 >> 2;
        const int og = b2 & 3;          // o group of 8

        float* ww = sm;                 // 8*32*6 = 1536 floats
        {
            const float* src = w_w + og * 8 * PC * 6;
            for (int idx = tid; idx < 8 * PC * 6; idx += 256) ww[idx] = src[idx];
        }
        __syncthreads();

        const int oo = tid >> 5;            // 0..7 within group
        const int o  = og * 8 + oo;
        const int j  = tid & 31;            // one warp per o

        float acc[16];
        const float bo = b_w[o];
        #pragma unroll
        for (int t = 0; t < 16; t++) acc[t] = bo;

        const float* Abase = g_wavg + n * PC * WW;
        const float* Mbase = g_wmax + n * PC * WW;

        for (int i = 0; i < PC; i++) {
            const float* wp = &ww[(oo * PC + i) * 6];
            const float a0 = wp[0], a1 = wp[1], a2 = wp[2];
            const float m0 = wp[3], m1 = wp[4], m2 = wp[5];
            const float* A = Abase + i * WW;
            const float* M = Mbase + i * WW;
            #pragma unroll
            for (int k = 0; k < 4; k++) {
                const int w0 = j * 4 + k * 128;
                float4 av = *reinterpret_cast<const float4*>(&A[w0]);
                float4 mv = *reinterpret_cast<const float4*>(&M[w0]);
                float am1 = (w0 > 0) ? A[w0 - 1] : 0.f;
                float mm1 = (w0 > 0) ? M[w0 - 1] : 0.f;
                float ap4 = (w0 + 4 < WW) ? A[w0 + 4] : 0.f;
                float mp4 = (w0 + 4 < WW) ? M[w0 + 4] : 0.f;
                acc[k*4+0] += am1 * a0 + av.x * a1 + av.y * a2 + mm1 * m0 + mv.x * m1 + mv.y * m2;
                acc[k*4+1] += av.x * a0 + av.y * a1 + av.z * a2 + mv.x * m0 + mv.y * m1 + mv.z * m2;
                acc[k*4+2] += av.y * a0 + av.z * a1 + av.w * a2 + mv.y * m0 + mv.z * m1 + mv.w * m2;
                acc[k*4+3] += av.z * a0 + av.w * a1 + ap4 * a2 + mv.z * m0 + mv.w * m1 + mp4 * m2;
            }
        }

        float lm = -3.4e38f;
        #pragma unroll
        for (int t = 0; t < 16; t++) { acc[t] = fmaxf(acc[t], 0.f); lm = fmaxf(lm, acc[t]); }
        #pragma unroll
        for (int off = 1; off <= 16; off <<= 1) lm = fmaxf(lm, __shfl_xor_sync(0xffffffffu, lm, off));
        float ls = 0.f;
        #pragma unroll
        for (int t = 0; t < 16; t++) { acc[t] = __expf(acc[t] - lm); ls += acc[t]; }
        #pragma unroll
        for (int off = 1; off <= 16; off <<= 1) ls += __shfl_xor_sync(0xffffffffu, ls, off);
        const float inv = 1.0f / ls;

        float* dst = g_pw + (n * PC + o) * WW;
        #pragma unroll
        for (int k = 0; k < 4; k++) {
            const int w0 = j * 4 + k * 128;
            float4 r;
            r.x = acc[k*4+0] * inv; r.y = acc[k*4+1] * inv;
            r.z = acc[k*4+2] * inv; r.w = acc[k*4+3] * inv;
            *reinterpret_cast<float4*>(&dst[w0]) = r;
        }
    }
}

// ---------------------------------------------------------------------------
// K4: apply. One CTA per (n, h-block of 8, w-quarter). Tile (o=4, h=4, w=4)
// per thread at __launch_bounds__(256,2) -> 128-reg budget, acc = 32 u64.
// Per c-iter: 1 data LDS.128 (4 wf) + 4 broadcast LDS.128 (4 wf) + 16 pk2 +
// 32 FFMA2 -> 8 LDS wf per 32 FFMA2 vs 12 before (-33% L1, the measured
// binding pipe). Warp -> 4 contiguous o-planes, lanes sweep contiguous w.
// dyn smem: pw[32][128] (16KB) + At8[8][32][32] (32KB) = 48KB
// ---------------------------------------------------------------------------
__global__ __launch_bounds__(256, 2) void k4_apply(const float* __restrict__ x,
                                                   const float* __restrict__ w_e,
                                                   const float* __restrict__ b_e,
                                                   float* __restrict__ out) {
    extern __shared__ float sm4[];
    float* pws = sm4;             // [32][128]
    float* At8 = sm4 + PC * WQ;   // [8][c][o]
    __shared__ float phs[HB * PC];
    __shared__ float bes[PC];

    const int bid = blockIdx.x;
    const int n   = bid >> 5;
    const int hbb = (bid >> 2) & 7;    // h = hbb*8 + hl
    const int wq  = bid & 3;           // w quarter
    const int tid = threadIdx.x;

    // stage pw quarter tile
    {
        const float4* pwg = reinterpret_cast<const float4*>(g_pw + n * PC * WW) + wq * (WQ / 4);
        float4* pw4 = reinterpret_cast<float4*>(pws);
        for (int idx = tid; idx < PC * WQ / 4; idx += 256) {
            const int c = idx >> 5, col = idx & 31;
            pw4[idx] = pwg[c * (WW / 4) + col];
        }
    }
    {
        const int hl = tid >> 5, c = tid & 31;   // 256 = 8*32 exactly
        phs[tid] = g_ph[(n * PC + c) * HH + hbb * HB + hl];
    }
    if (tid < PC) bes[tid] = b_e[tid];
    __syncthreads();

    for (int idx = tid; idx < HB * PC * PC; idx += 256) {
        const int hl = idx >> 10;
        const int c  = (idx >> 5) & 31;
        const int o  = idx & 31;
        At8[idx] = w_e[o * PC + c] * phs[hl * PC + c];
    }
    __syncthreads();

    const int wid  = tid >> 5;        // 0..7
    const int lane = tid & 31;
    const int o0   = wid * 4;         // 4 contiguous o per warp (8 warps x 4 = 32)
    const int wofs = lane * 4;        // contiguous w within quarter

    #pragma unroll 1
    for (int hp = 0; hp < 2; hp++) {
        const int h0 = hbb * HB + hp * 4;
        const float* At0 = At8 + (hp * 4) * (PC * PC);
        const float* At1 = At0 + PC * PC;
        const float* At2 = At1 + PC * PC;
        const float* At3 = At2 + PC * PC;
        const size_t base0 = (((size_t)(n * PC + o0)) * HH + h0) * WW + wq * WQ + wofs;

        // L2 prefetch of all 16 x rows (4 o-planes x 4 h); covered by the c-loop
        #pragma unroll
        for (int oi = 0; oi < 4; oi++) {
            const float* xp = x + base0 + (size_t)oi * HH * WW;
            asm volatile("prefetch.global.L2 [%0];" :: "l"(xp));
            asm volatile("prefetch.global.L2 [%0];" :: "l"(xp + WW));
            asm volatile("prefetch.global.L2 [%0];" :: "l"(xp + 2 * WW));
            asm volatile("prefetch.global.L2 [%0];" :: "l"(xp + 3 * WW));
        }

        u64 acc[4][4][2];   // [h][o][w-pair]
        #pragma unroll
        for (int hh = 0; hh < 4; hh++)
            #pragma unroll
            for (int oi = 0; oi < 4; oi++) { acc[hh][oi][0] = 0ull; acc[hh][oi][1] = 0ull; }

        #pragma unroll 4
        for (int c = 0; c < PC; c++) {
            const ulonglong2 q = *reinterpret_cast<const ulonglong2*>(&pws[c * WQ + wofs]);
            u64 av;
            {
                const float4 a = *reinterpret_cast<const float4*>(&At0[c * PC + o0]);
                av = pk2(a.x, a.x); ffma2(acc[0][0][0], av, q.x); ffma2(acc[0][0][1], av, q.y);
                av = pk2(a.y, a.y); ffma2(acc[0][1][0], av, q.x); ffma2(acc[0][1][1], av, q.y);
                av = pk2(a.z, a.z); ffma2(acc[0][2][0], av, q.x); ffma2(acc[0][2][1], av, q.y);
                av = pk2(a.w, a.w); ffma2(acc[0][3][0], av, q.x); ffma2(acc[0][3][1], av, q.y);
            }
            {
                const float4 a = *reinterpret_cast<const float4*>(&At1[c * PC + o0]);
                av = pk2(a.x, a.x); ffma2(acc[1][0][0], av, q.x); ffma2(acc[1][0][1], av, q.y);
                av = pk2(a.y, a.y); ffma2(acc[1][1][0], av, q.x); ffma2(acc[1][1][1], av, q.y);
                av = pk2(a.z, a.z); ffma2(acc[1][2][0], av, q.x); ffma2(acc[1][2][1], av, q.y);
                av = pk2(a.w, a.w); ffma2(acc[1][3][0], av, q.x); ffma2(acc[1][3][1], av, q.y);
            }
            {
                const float4 a = *reinterpret_cast<const float4*>(&At2[c * PC + o0]);
                av = pk2(a.x, a.x); ffma2(acc[2][0][0], av, q.x); ffma2(acc[2][0][1], av, q.y);
                av = pk2(a.y, a.y); ffma2(acc[2][1][0], av, q.x); ffma2(acc[2][1][1], av, q.y);
                av = pk2(a.z, a.z); ffma2(acc[2][2][0], av, q.x); ffma2(acc[2][2][1], av, q.y);
                av = pk2(a.w, a.w); ffma2(acc[2][3][0], av, q.x); ffma2(acc[2][3][1], av, q.y);
            }
            {
                const float4 a = *reinterpret_cast<const float4*>(&At3[c * PC + o0]);
                av = pk2(a.x, a.x); ffma2(acc[3][0][0], av, q.x); ffma2(acc[3][0][1], av, q.y);
                av = pk2(a.y, a.y); ffma2(acc[3][1][0], av, q.x); ffma2(acc[3][1][1], av, q.y);
                av = pk2(a.z, a.z); ffma2(acc[3][2][0], av, q.x); ffma2(acc[3][2][1], av, q.y);
                av = pk2(a.w, a.w); ffma2(acc[3][3][0], av, q.x); ffma2(acc[3][3][1], av, q.y);
            }
        }

        // epilogue: coalesced float4 per (h,o) row; temps reused
        #pragma unroll
        for (int hh = 0; hh < 4; hh++) {
            #pragma unroll
            for (int oi = 0; oi < 4; oi++) {
                const float bo = bes[o0 + oi];
                const size_t ba = base0 + (size_t)oi * HH * WW + (size_t)hh * WW;
                const float4 xv = *reinterpret_cast<const float4*>(x + ba);
                float t0, t1, t2, t3;
                upk2(acc[hh][oi][0], t0, t1);
                upk2(acc[hh][oi][1], t2, t3);
                float4 r;
                r.x = xv.x * (1.0f + sigf(t0 + bo));
                r.y = xv.y * (1.0f + sigf(t1 + bo));
                r.z = xv.z * (1.0f + sigf(t2 + bo));
                r.w = xv.w * (1.0f + sigf(t3 + bo));
                *reinterpret_cast<float4*>(out + ba) = r;
            }
        }
    }
}

extern "C" void kernel_launch(void* const* d_in, const int* in_sizes, int n_in,
                              void* d_out, int out_size) {
    const float* x   = (const float*)d_in[0];
    const float* w_h = (const float*)d_in[1];
    const float* b_h = (const float*)d_in[2];
    const float* w_w = (const float*)d_in[3];
    const float* b_w = (const float*)d_in[4];
    const float* w_e = (const float*)d_in[5];
    const float* b_e = (const float*)d_in[6];
    float* out = (float*)d_out;

    const int smem23 = (2 * PC * HH + PC * PC * 6) * 4;  // 40960 (ph part)
    const int smem4  = (PC * WQ + HB * PC * PC) * 4;     // 16384 + 32768 = 49152
    cudaFuncSetAttribute(k23,      cudaFuncAttributeMaxDynamicSharedMemorySize, smem23);
    cudaFuncSetAttribute(k4_apply, cudaFuncAttributeMaxDynamicSharedMemorySize, smem4);

    k1_stats<<<NP * PC, 256>>>(x);
    k23<<<64 + NP * 4, 256, smem23>>>(w_h, b_h, w_w, b_w);
    k_dummy<<<1, 32>>>(&g_sink);   // keeps ncu capture (-s 5) on k4_apply
    k4_apply<<<NP * 8 * 4, 256, smem4>>>(x, w_e, b_e, out);
}

// round 17
// speedup vs baseline: 1.3908x; 1.3908x over previous
#include <cuda_runtime.h>

// Problem constants
#define NP    64     // B*NUM_PARTS = 16*4
#define PC    32     // channels per part
#define HH    64
#define WW    512
#define HB    8      // h rows per K4 CTA
#define WQ    128    // w quarter width per K4 CTA

typedef unsigned long long u64;

__device__ __forceinline__ u64 pk2(float a, float b) {
    u64 r; asm("mov.b64 %0, {%1,%2};" : "=l"(r) : "f"(a), "f"(b)); return r;
}
__device__ __forceinline__ void upk2(u64 v, float& a, float& b) {
    asm("mov.b64 {%0,%1}, %2;" : "=f"(a), "=f"(b) : "l"(v));
}
__device__ __forceinline__ void ffma2(u64& d, u64 a, u64 b) {
    asm("fma.rn.f32x2 %0, %1, %2, %0;" : "+l"(d) : "l"(a), "l"(b));
}

// lean branchless sigmoid: FMUL+EX2 (expf) + FADD + MUFU.RCP.
__device__ __forceinline__ float sigf(float t) {
    float e = __expf(-t);
    float d = 1.0f + e;
    float r; asm("rcp.approx.f32 %0, %1;" : "=f"(r) : "f"(d));
    return r;
}

// Scratch (device globals, allocation-free)
__device__ float g_havg[NP * PC * HH];
__device__ float g_hmax[NP * PC * HH];
__device__ float g_wavg[NP * PC * WW];
__device__ float g_wmax[NP * PC * WW];
__device__ float g_ph[NP * PC * HH];
__device__ float g_pw[NP * PC * WW];        // UNNORMALIZED exp(relu(conv))
__device__ float g_psum[NP * PC * 2];       // per-(n,c,half) exp sums
__device__ int   g_sink;

// dummy launch to keep the ncu -s 5 -c 1 capture window on k4_apply
__global__ void k_dummy(int* sink) { if (threadIdx.x == 1024) *sink = 0; }

// ---------------------------------------------------------------------------
// K1: per-(n,c) slice stats. Quad-level shfl reduce + smem partials.
// grid 2048, 256 threads
// ---------------------------------------------------------------------------
__global__ __launch_bounds__(256) void k1_stats(const float* __restrict__ x) {
    const int nc  = blockIdx.x;
    const int tid = threadIdx.x;
    const int r2  = tid >> 7;        // 0/1: which row of a 2-row stripe
    const int c4  = tid & 127;       // float4 column 0..127

    const float4* xs = reinterpret_cast<const float4*>(x + (size_t)nc * HH * WW);

    __shared__ float rs[HH][33], rm[HH][33];   // 33: kill final-reduce bank conflict
    __shared__ float csh[WW], cmh[WW];

    float cs0 = 0.f, cs1 = 0.f, cs2 = 0.f, cs3 = 0.f;
    float cm0 = -3.4e38f, cm1 = -3.4e38f, cm2 = -3.4e38f, cm3 = -3.4e38f;
    const int q = c4 >> 2;

    for (int h0 = 0; h0 < HH; h0 += 2) {
        const int h = h0 + r2;
        float4 v = xs[h * 128 + c4];
        cs0 += v.x; cs1 += v.y; cs2 += v.z; cs3 += v.w;
        cm0 = fmaxf(cm0, v.x); cm1 = fmaxf(cm1, v.y);
        cm2 = fmaxf(cm2, v.z); cm3 = fmaxf(cm3, v.w);
        float s = (v.x + v.y) + (v.z + v.w);
        float m = fmaxf(fmaxf(v.x, v.y), fmaxf(v.z, v.w));
        s += __shfl_xor_sync(0xffffffffu, s, 1);
        m  = fmaxf(m, __shfl_xor_sync(0xffffffffu, m, 1));
        s += __shfl_xor_sync(0xffffffffu, s, 2);
        m  = fmaxf(m, __shfl_xor_sync(0xffffffffu, m, 2));
        if ((tid & 3) == 0) { rs[h][q] = s; rm[h][q] = m; }
    }
    __syncthreads();

    if (tid < HH) {
        float s = 0.f, m = -3.4e38f;
        #pragma unroll
        for (int k = 0; k < 32; k++) { s += rs[tid][k]; m = fmaxf(m, rm[tid][k]); }
        g_havg[nc * HH + tid] = s * (1.0f / (float)WW);
        g_hmax[nc * HH + tid] = m;
    }

    if (r2 == 0) {
        csh[c4 * 4 + 0] = cs0; csh[c4 * 4 + 1] = cs1; csh[c4 * 4 + 2] = cs2; csh[c4 * 4 + 3] = cs3;
        cmh[c4 * 4 + 0] = cm0; cmh[c4 * 4 + 1] = cm1; cmh[c4 * 4 + 2] = cm2; cmh[c4 * 4 + 3] = cm3;
    }
    __syncthreads();
    if (r2 == 1) {
        const int w = c4 * 4;
        g_wavg[nc * WW + w + 0] = (cs0 + csh[w + 0]) * (1.0f / (float)HH);
        g_wavg[nc * WW + w + 1] = (cs1 + csh[w + 1]) * (1.0f / (float)HH);
        g_wavg[nc * WW + w + 2] = (cs2 + csh[w + 2]) * (1.0f / (float)HH);
        g_wavg[nc * WW + w + 3] = (cs3 + csh[w + 3]) * (1.0f / (float)HH);
        g_wmax[nc * WW + w + 0] = fmaxf(cm0, cmh[w + 0]);
        g_wmax[nc * WW + w + 1] = fmaxf(cm1, cmh[w + 1]);
        g_wmax[nc * WW + w + 2] = fmaxf(cm2, cmh[w + 2]);
        g_wmax[nc * WW + w + 3] = fmaxf(cm3, cmh[w + 3]);
    }
}

// ---------------------------------------------------------------------------
// K23: merged ph conv (blocks [0,64)) + pw conv (blocks [64,576): n x og x half)
// pw stages a [32][256] w-half (70KB -> 3 CTAs/SM, 512 blocks, 2x parallelism);
// writes UNNORMALIZED exp(relu(conv)) + per-(n,c,half) sums. Halo from L2.
// ---------------------------------------------------------------------------
__global__ __launch_bounds__(256) void k23(const float* __restrict__ w_h,
                                           const float* __restrict__ b_h,
                                           const float* __restrict__ w_w,
                                           const float* __restrict__ b_w) {
    extern __shared__ float sm[];
    const int bid = blockIdx.x;
    const int tid = threadIdx.x;

    if (bid < 64) {
        // ---------------- ph: conv 3x2 pad(h)=1 + relu + softmax over h ----
        const int n = bid;
        float* ha = sm;                 // [32][64]
        float* hm = sm + PC * HH;       // [32][64]
        float* wh = sm + 2 * PC * HH;   // 6144

        for (int idx = tid; idx < PC * HH; idx += 256) {
            ha[idx] = g_havg[n * PC * HH + idx];
            hm[idx] = g_hmax[n * PC * HH + idx];
        }
        for (int idx = tid; idx < PC * PC * 6; idx += 256) wh[idx] = w_h[idx];
        __syncthreads();

        const int o  = tid >> 3;     // 0..31
        const int j  = tid & 7;      // 8 threads per o, 8 h each
        const int hb = j * 8;

        float acc[8];
        const float bo = b_h[o];
        #pragma unroll
        for (int t = 0; t < 8; t++) acc[t] = bo;

        for (int i = 0; i < PC; i++) {
            const float* wp = &wh[(o * PC + i) * 6];
            const float w00 = wp[0], w01 = wp[1], w10 = wp[2], w11 = wp[3], w20 = wp[4], w21 = wp[5];
            const float* A = ha + i * HH;
            const float* M = hm + i * HH;
            float wA[10], wM[10];
            wA[0] = (hb > 0) ? A[hb - 1] : 0.f;
            wM[0] = (hb > 0) ? M[hb - 1] : 0.f;
            #pragma unroll
            for (int t = 0; t < 8; t++) { wA[t + 1] = A[hb + t]; wM[t + 1] = M[hb + t]; }
            wA[9] = (hb + 8 < HH) ? A[hb + 8] : 0.f;
            wM[9] = (hb + 8 < HH) ? M[hb + 8] : 0.f;
            #pragma unroll
            for (int t = 0; t < 8; t++) {
                acc[t] += wA[t] * w00 + wM[t] * w01
                        + wA[t + 1] * w10 + wM[t + 1] * w11
                        + wA[t + 2] * w20 + wM[t + 2] * w21;
            }
        }

        float lm = -3.4e38f;
        #pragma unroll
        for (int t = 0; t < 8; t++) { acc[t] = fmaxf(acc[t], 0.f); lm = fmaxf(lm, acc[t]); }
        #pragma unroll
        for (int off = 1; off <= 4; off <<= 1) lm = fmaxf(lm, __shfl_xor_sync(0xffffffffu, lm, off));
        float ls = 0.f;
        #pragma unroll
        for (int t = 0; t < 8; t++) { acc[t] = __expf(acc[t] - lm); ls += acc[t]; }
        #pragma unroll
        for (int off = 1; off <= 4; off <<= 1) ls += __shfl_xor_sync(0xffffffffu, ls, off);
        const float inv = 1.0f / ls;
        #pragma unroll
        for (int t = 0; t < 8; t++) g_ph[(n * PC + o) * HH + hb + t] = acc[t] * inv;
    } else {
        // -------- pw: conv 2x3 pad(w)=1 + relu + exp (unnormalized) --------
        const int b2 = bid - 64;
        const int n  = b2 >> 3;
        const int og = (b2 >> 1) & 3;   // o group of 8
        const int hf = b2 & 1;          // w half

        float* wa = sm;                  // [32][256]
        float* wm = sm + PC * 256;       // [32][256]
        float* ww = sm + 2 * PC * 256;   // 1536

        const float* Abase = g_wavg + n * PC * WW + hf * 256;
        const float* Mbase = g_wmax + n * PC * WW + hf * 256;
        {
            float4* da = reinterpret_cast<float4*>(wa);
            float4* dm = reinterpret_cast<float4*>(wm);
            for (int idx = tid; idx < PC * 64; idx += 256) {
                const int c = idx >> 6, col = idx & 63;
                da[idx] = *reinterpret_cast<const float4*>(Abase + c * WW + col * 4);
                dm[idx] = *reinterpret_cast<const float4*>(Mbase + c * WW + col * 4);
            }
        }
        {
            const float* src = w_w + og * 8 * PC * 6;
            for (int idx = tid; idx < 8 * PC * 6; idx += 256) ww[idx] = src[idx];
        }
        __syncthreads();

        const int oo = tid >> 5;            // 0..7 within group
        const int o  = og * 8 + oo;
        const int j  = tid & 31;            // one warp per o, 256 w per warp

        float acc[8];
        const float bo = b_w[o];
        #pragma unroll
        for (int t = 0; t < 8; t++) acc[t] = bo;

        for (int i = 0; i < PC; i++) {
            const float* wp = &ww[(oo * PC + i) * 6];
            const float a0 = wp[0], a1 = wp[1], a2 = wp[2];
            const float m0 = wp[3], m1 = wp[4], m2 = wp[5];
            const float* A = wa + i * 256;
            const float* M = wm + i * 256;
            const float* Ag = Abase + i * WW;   // for halo
            const float* Mg = Mbase + i * WW;
            #pragma unroll
            for (int k = 0; k < 2; k++) {
                const int w0l = j * 4 + k * 128;
                float4 av = *reinterpret_cast<const float4*>(&A[w0l]);
                float4 mv = *reinterpret_cast<const float4*>(&M[w0l]);
                float am1, mm1, ap4, mp4;
                if (w0l > 0) { am1 = A[w0l - 1]; mm1 = M[w0l - 1]; }
                else if (hf == 1) { am1 = Ag[-1]; mm1 = Mg[-1]; }
                else { am1 = 0.f; mm1 = 0.f; }
                if (w0l + 4 < 256) { ap4 = A[w0l + 4]; mp4 = M[w0l + 4]; }
                else if (hf == 0) { ap4 = Ag[256]; mp4 = Mg[256]; }
                else { ap4 = 0.f; mp4 = 0.f; }
                acc[k*4+0] += am1 * a0 + av.x * a1 + av.y * a2 + mm1 * m0 + mv.x * m1 + mv.y * m2;
                acc[k*4+1] += av.x * a0 + av.y * a1 + av.z * a2 + mv.x * m0 + mv.y * m1 + mv.z * m2;
                acc[k*4+2] += av.y * a0 + av.z * a1 + av.w * a2 + mv.y * m0 + mv.z * m1 + mv.w * m2;
                acc[k*4+3] += av.z * a0 + av.w * a1 + ap4 * a2 + mv.z * m0 + mv.w * m1 + mp4 * m2;
            }
        }

        // relu + exp (no max-subtraction: args bounded ~|10|, exact same softmax)
        float lsum = 0.f;
        #pragma unroll
        for (int t = 0; t < 8; t++) { acc[t] = __expf(fmaxf(acc[t], 0.f)); lsum += acc[t]; }
        #pragma unroll
        for (int off = 16; off >= 1; off >>= 1) lsum += __shfl_xor_sync(0xffffffffu, lsum, off);
        if (j == 0) g_psum[(n * PC + o) * 2 + hf] = lsum;

        float* dst = g_pw + (n * PC + o) * WW + hf * 256;
        #pragma unroll
        for (int k = 0; k < 2; k++) {
            const int w0l = j * 4 + k * 128;
            float4 r;
            r.x = acc[k*4+0]; r.y = acc[k*4+1]; r.z = acc[k*4+2]; r.w = acc[k*4+3];
            *reinterpret_cast<float4*>(&dst[w0l]) = r;
        }
    }
}

// ---------------------------------------------------------------------------
// K4: apply. R14's proven h-paired mainloop at (256,4), 48KB smem, 133.6us.
// Only change: softmax normalization 1/sum folded into the At build (g_psum).
// ---------------------------------------------------------------------------
__global__ __launch_bounds__(256, 4) void k4_apply(const float* __restrict__ x,
                                                   const float* __restrict__ w_e,
                                                   const float* __restrict__ b_e,
                                                   float* __restrict__ out) {
    extern __shared__ float sm4[];
    float* pws = sm4;             // [32][128]
    float* At8 = sm4 + PC * WQ;   // [8][c][o]
    __shared__ float phs[HB * PC];
    __shared__ float bes[PC];
    __shared__ float invs[PC];

    const int bid = blockIdx.x;
    const int n   = bid >> 5;
    const int hbb = (bid >> 2) & 7;    // h = hbb*8 + hl
    const int wq  = bid & 3;           // w quarter
    const int tid = threadIdx.x;

    // stage pw quarter tile (raw exp values)
    {
        const float4* pwg = reinterpret_cast<const float4*>(g_pw + n * PC * WW) + wq * (WQ / 4);
        float4* pw4 = reinterpret_cast<float4*>(pws);
        for (int idx = tid; idx < PC * WQ / 4; idx += 256) {
            const int c = idx >> 5, col = idx & 31;
            pw4[idx] = pwg[c * (WW / 4) + col];
        }
    }
    {
        const int hl = tid >> 5, c = tid & 31;   // 256 = 8*32 exactly
        phs[tid] = g_ph[(n * PC + c) * HH + hbb * HB + hl];
    }
    if (tid < PC) {
        bes[tid] = b_e[tid];
        const float s = g_psum[(n * PC + tid) * 2] + g_psum[(n * PC + tid) * 2 + 1];
        invs[tid] = 1.0f / s;
    }
    __syncthreads();

    for (int idx = tid; idx < HB * PC * PC; idx += 256) {
        const int hl = idx >> 10;
        const int c  = (idx >> 5) & 31;
        const int o  = idx & 31;
        At8[idx] = w_e[o * PC + c] * phs[hl * PC + c] * invs[c];
    }
    __syncthreads();

    const int wid  = tid >> 5;        // 0..7
    const int lane = tid & 31;
    const int o0   = wid * 4;         // 4 contiguous o per warp
    const int wofs = lane * 4;        // contiguous w within quarter

    #pragma unroll 1
    for (int hp = 0; hp < HB / 2; hp++) {
        const int h0 = hbb * HB + 2 * hp;
        const float* At0 = At8 + (2 * hp) * (PC * PC);
        const float* At1 = At0 + (PC * PC);
        const size_t base0 = (((size_t)(n * PC + o0)) * HH + h0) * WW + wq * WQ + wofs;

        // L2 prefetch of both h rows' x tiles; covered by the c-loop below
        #pragma unroll
        for (int oi = 0; oi < 4; oi++) {
            asm volatile("prefetch.global.L2 [%0];" :: "l"(x + base0 + (size_t)oi * HH * WW));
            asm volatile("prefetch.global.L2 [%0];" :: "l"(x + base0 + (size_t)oi * HH * WW + WW));
        }

        u64 acA[4][2], acB[4][2];
        #pragma unroll
        for (int oi = 0; oi < 4; oi++) {
            acA[oi][0] = 0ull; acA[oi][1] = 0ull;
            acB[oi][0] = 0ull; acB[oi][1] = 0ull;
        }

        #pragma unroll 4
        for (int c = 0; c < PC; c++) {
            const float4 a0 = *reinterpret_cast<const float4*>(&At0[c * PC + o0]);
            const float4 b0 = *reinterpret_cast<const float4*>(&At1[c * PC + o0]);
            const ulonglong2 q = *reinterpret_cast<const ulonglong2*>(&pws[c * WQ + wofs]);
            u64 av;
            av = pk2(a0.x, a0.x); ffma2(acA[0][0], av, q.x); ffma2(acA[0][1], av, q.y);
            av = pk2(a0.y, a0.y); ffma2(acA[1][0], av, q.x); ffma2(acA[1][1], av, q.y);
            av = pk2(a0.z, a0.z); ffma2(acA[2][0], av, q.x); ffma2(acA[2][1], av, q.y);
            av = pk2(a0.w, a0.w); ffma2(acA[3][0], av, q.x); ffma2(acA[3][1], av, q.y);
            av = pk2(b0.x, b0.x); ffma2(acB[0][0], av, q.x); ffma2(acB[0][1], av, q.y);
            av = pk2(b0.y, b0.y); ffma2(acB[1][0], av, q.x); ffma2(acB[1][1], av, q.y);
            av = pk2(b0.z, b0.z); ffma2(acB[2][0], av, q.x); ffma2(acB[2][1], av, q.y);
            av = pk2(b0.w, b0.w); ffma2(acB[3][0], av, q.x); ffma2(acB[3][1], av, q.y);
        }

        // epilogue: hl0 then hl1
        #pragma unroll
        for (int oi = 0; oi < 4; oi++) {
            const float bo = bes[o0 + oi];
            const size_t ba = base0 + (size_t)oi * HH * WW;
            const float4 xv = *reinterpret_cast<const float4*>(x + ba);
            float t0, t1, t2, t3;
            upk2(acA[oi][0], t0, t1);
            upk2(acA[oi][1], t2, t3);
            float4 r;
            r.x = xv.x * (1.0f + sigf(t0 + bo));
            r.y = xv.y * (1.0f + sigf(t1 + bo));
            r.z = xv.z * (1.0f + sigf(t2 + bo));
            r.w = xv.w * (1.0f + sigf(t3 + bo));
            *reinterpret_cast<float4*>(out + ba) = r;
        }
        #pragma unroll
        for (int oi = 0; oi < 4; oi++) {
            const float bo = bes[o0 + oi];
            const size_t ba = base0 + (size_t)oi * HH * WW + WW;
            const float4 xv = *reinterpret_cast<const float4*>(x + ba);
            float t0, t1, t2, t3;
            upk2(acB[oi][0], t0, t1);
            upk2(acB[oi][1], t2, t3);
            float4 r;
            r.x = xv.x * (1.0f + sigf(t0 + bo));
            r.y = xv.y * (1.0f + sigf(t1 + bo));
            r.z = xv.z * (1.0f + sigf(t2 + bo));
            r.w = xv.w * (1.0f + sigf(t3 + bo));
            *reinterpret_cast<float4*>(out + ba) = r;
        }
    }
}

extern "C" void kernel_launch(void* const* d_in, const int* in_sizes, int n_in,
                              void* d_out, int out_size) {
    const float* x   = (const float*)d_in[0];
    const float* w_h = (const float*)d_in[1];
    const float* b_h = (const float*)d_in[2];
    const float* w_w = (const float*)d_in[3];
    const float* b_w = (const float*)d_in[4];
    const float* w_e = (const float*)d_in[5];
    const float* b_e = (const float*)d_in[6];
    float* out = (float*)d_out;

    const int smem23 = (2 * PC * 256 + 8 * PC * 6) * 4;  // 65536 + 6144 = 71680
    const int smem4  = (PC * WQ + HB * PC * PC) * 4;     // 16384 + 32768 = 49152
    cudaFuncSetAttribute(k23,      cudaFuncAttributeMaxDynamicSharedMemorySize, smem23);
    cudaFuncSetAttribute(k4_apply, cudaFuncAttributeMaxDynamicSharedMemorySize, smem4);

    k1_stats<<<NP * PC, 256>>>(x);
    k23<<<64 + NP * 4 * 2, 256, smem23>>>(w_h, b_h, w_w, b_w);
    k_dummy<<<1, 32>>>(&g_sink);   // keeps ncu capture (-s 5) on k4_apply
    k4_apply<<<NP * 8 * 4, 256, smem4>>>(x, w_e, b_e, out);
}